// round 15
// baseline (speedup 1.0000x reference)
#include <cuda_runtime.h>
#include <cuda_fp16.h>
#include <math.h>
#include <stdint.h>

#define D_MODEL 1024
#define SEQ     4096
#define BATCH   4
#define NTOK    16384
#define NHEADS  16
#define EPS     1e-6f
#define KCH     4

// ---------------- scratch ----------------
__device__ __half g_Xh[(size_t)NTOK * D_MODEL];
__device__ __half g_Ah[(size_t)NTOK * D_MODEL];
__device__ __half g_Qh[(size_t)NTOK * D_MODEL];
__device__ __half g_Kh[(size_t)NTOK * D_MODEL];
__device__ __half g_Vh[(size_t)NTOK * D_MODEL];
__device__ __half g_Wh[4][(size_t)D_MODEL * D_MODEL];   // transposed [n][k]
__device__ float  g_bkv[2 * D_MODEL];
__device__ float  g_kvp[KCH * 64 * 4096];
__device__ float  g_ksp[KCH * 64 * 64];
__device__ __half g_kvTh[64 * 4096];                    // kv^T per bh: [e][d]
__device__ float  g_ks[64 * 64];

// ---------------- fp16 TC GEMM: 256 thr, warp tile 64x32, K-tile 64 ----------------
#define RS     72
#define RSB    144
#define MATB   (128 * RSB)
#define STAGEB (2 * MATB)
#define NSTAGE 3
#define GEMM_SMEM (NSTAGE * STAGEB)
#define NKT    16

__device__ __forceinline__ void cpasync16(uint32_t dst, const void* src) {
    asm volatile("cp.async.cg.shared.global [%0], [%1], 16;\n" ::"r"(dst), "l"(src));
}

__device__ __forceinline__ void load_tile(uint32_t sst, const __half* __restrict__ A,
                                          const __half* __restrict__ Bt,
                                          int m0, int n0, int kt, int tid) {
    const __half* Asrc = A + (size_t)m0 * 1024 + kt * 64;
    const __half* Bsrc = Bt + (size_t)n0 * 1024 + kt * 64;
#pragma unroll
    for (int j = 0; j < 4; j++) {
        int c = tid + j * 256;
        int row = c >> 3, kc = (c & 7) * 8;
        cpasync16(sst + (uint32_t)(row * RSB + kc * 2), Asrc + (size_t)row * 1024 + kc);
    }
#pragma unroll
    for (int j = 0; j < 4; j++) {
        int c = tid + j * 256;
        int row = c >> 3, kc = (c & 7) * 8;
        cpasync16(sst + (uint32_t)(MATB + row * RSB + kc * 2),
                  Bsrc + (size_t)row * 1024 + kc);
    }
    asm volatile("cp.async.commit_group;\n" ::: "memory");
}

#define LDMX4(dst, addr)                                                       \
    asm volatile("ldmatrix.sync.aligned.m8n8.x4.shared.b16 {%0,%1,%2,%3}, [%4];" \
                 : "=r"((dst)[0]), "=r"((dst)[1]), "=r"((dst)[2]), "=r"((dst)[3]) \
                 : "r"(addr))

#define HMMA(acc, a, b0r, b1r)                                                 \
    asm volatile("mma.sync.aligned.m16n8k16.row.col.f32.f16.f16.f32 "          \
                 "{%0,%1,%2,%3}, {%4,%5,%6,%7}, {%8,%9}, {%0,%1,%2,%3};"       \
                 : "+f"((acc)[0]), "+f"((acc)[1]), "+f"((acc)[2]), "+f"((acc)[3]) \
                 : "r"((a)[0]), "r"((a)[1]), "r"((a)[2]), "r"((a)[3]),          \
                   "r"(b0r), "r"(b1r))

// seg 0: n0 in [0,1024) -> C0 with fmap0 ; seg 1: n0 in [1024,2048) -> C1 with fmap1
template <typename OutT>
__global__ void __launch_bounds__(256, 2) gemm_h256(const __half* __restrict__ A,
                                                    const __half* __restrict__ Bt,
                                                    const float* __restrict__ bias,
                                                    OutT* __restrict__ C0,
                                                    OutT* __restrict__ C1,
                                                    int fmap0, int fmap1) {
    extern __shared__ __align__(128) char smem[];
    uint32_t sb;
    asm("{ .reg .u64 t; cvta.to.shared.u64 t, %1; cvt.u32.u64 %0, t; }" : "=r"(sb) : "l"(smem));

    const int tid = threadIdx.x;
    const int lane = tid & 31, w = tid >> 5;
    const int wm = w & 1;
    const int wn = w >> 1;
    const int m0 = blockIdx.y * 128, n0 = blockIdx.x * 128;

    const uint32_t aOff = (uint32_t)(((wm * 64 + (lane & 15)) * RS + (lane >> 4) * 8) * 2);
    const uint32_t bOff = (uint32_t)(MATB +
                                     ((wn * 32 + ((lane >> 4) & 1) * 8 + (lane & 7)) * RS +
                                      ((lane >> 3) & 1) * 8) * 2);

    float acc[4][4][4];
#pragma unroll
    for (int i = 0; i < 4; i++)
#pragma unroll
        for (int j = 0; j < 4; j++)
#pragma unroll
            for (int r = 0; r < 4; r++) acc[i][j][r] = 0.0f;

    load_tile(sb, A, Bt, m0, n0, 0, tid);
    load_tile(sb + STAGEB, A, Bt, m0, n0, 1, tid);

    int st = 0;
    for (int kt = 0; kt < NKT; kt++) {
        if (kt < NKT - 1)
            asm volatile("cp.async.wait_group 1;\n" ::: "memory");
        else
            asm volatile("cp.async.wait_group 0;\n" ::: "memory");
        __syncthreads();
        if (kt + 2 < NKT) {
            int nst = st + 2; if (nst >= NSTAGE) nst -= NSTAGE;
            load_tile(sb + (uint32_t)nst * STAGEB, A, Bt, m0, n0, kt + 2, tid);
        }
        const uint32_t cs = sb + (uint32_t)st * STAGEB;

#pragma unroll
        for (int ks = 0; ks < 4; ks++) {
            uint32_t a[4][4];
#pragma unroll
            for (int mf = 0; mf < 4; mf++)
                LDMX4(a[mf], cs + aOff + (uint32_t)(mf * 16 * RSB + ks * 32));
#pragma unroll
            for (int nfp = 0; nfp < 2; nfp++) {
                uint32_t b[4];
                LDMX4(b, cs + bOff + (uint32_t)(nfp * 16 * RSB + ks * 32));
#pragma unroll
                for (int mf = 0; mf < 4; mf++) {
                    HMMA(acc[mf][nfp * 2], a[mf], b[0], b[1]);
                    HMMA(acc[mf][nfp * 2 + 1], a[mf], b[2], b[3]);
                }
            }
        }
        st++; if (st >= NSTAGE) st -= NSTAGE;
    }

    OutT* C = (n0 < 1024) ? C0 : C1;
    const int ncol0 = (n0 < 1024) ? n0 : n0 - 1024;
    const bool fmap = (n0 < 1024) ? (fmap0 != 0) : (fmap1 != 0);

    const int gr = lane >> 2, gc2 = (lane & 3) * 2;
#pragma unroll
    for (int mf = 0; mf < 4; mf++) {
        int r0 = m0 + wm * 64 + mf * 16 + gr;
#pragma unroll
        for (int nf = 0; nf < 4; nf++) {
            int colg = n0 + wn * 32 + nf * 8 + gc2;
            int col = ncol0 + wn * 32 + nf * 8 + gc2;
            float2 bb = *(const float2*)(bias + colg);
            float v0 = acc[mf][nf][0] + bb.x;
            float v1 = acc[mf][nf][1] + bb.y;
            float v2 = acc[mf][nf][2] + bb.x;
            float v3 = acc[mf][nf][3] + bb.y;
            if (fmap) {
                v0 = (v0 > 0.0f) ? v0 + 1.0f : expf(v0);
                v1 = (v1 > 0.0f) ? v1 + 1.0f : expf(v1);
                v2 = (v2 > 0.0f) ? v2 + 1.0f : expf(v2);
                v3 = (v3 > 0.0f) ? v3 + 1.0f : expf(v3);
            }
            if (sizeof(OutT) == 2) {
                *(__half2*)((__half*)C + (size_t)r0 * 1024 + col) = __floats2half2_rn(v0, v1);
                *(__half2*)((__half*)C + (size_t)(r0 + 8) * 1024 + col) = __floats2half2_rn(v2, v3);
            } else {
                float2 o0 = {v0, v1}, o1 = {v2, v3};
                *(float2*)((float*)C + (size_t)r0 * 1024 + col) = o0;
                *(float2*)((float*)C + (size_t)(r0 + 8) * 1024 + col) = o1;
            }
        }
    }
}

// ---------------- conversions ----------------
__global__ void to_half_kernel(const float4* __restrict__ in, __half2* __restrict__ out,
                               int n4) {
    int i = blockIdx.x * blockDim.x + threadIdx.x;
    if (i >= n4) return;
    float4 v = in[i];
    out[i * 2]     = __floats2half2_rn(v.x, v.y);
    out[i * 2 + 1] = __floats2half2_rn(v.z, v.w);
}

__global__ void transpose_half4(const float* __restrict__ W0, const float* __restrict__ W1,
                                const float* __restrict__ W2, const float* __restrict__ W3,
                                __half* __restrict__ Wt) {
    const float* W = (blockIdx.z == 0) ? W0 : (blockIdx.z == 1) ? W1
                     : (blockIdx.z == 2) ? W2 : W3;
    __half* Wo = Wt + (size_t)blockIdx.z * D_MODEL * D_MODEL;
    __shared__ float t[32][33];
    const int bx = blockIdx.x * 32, by = blockIdx.y * 32;
    const int tx = threadIdx.x, ty = threadIdx.y;
#pragma unroll
    for (int j = 0; j < 32; j += 8)
        t[ty + j][tx] = W[(size_t)(by + ty + j) * 1024 + bx + tx];
    __syncthreads();
#pragma unroll
    for (int j = 0; j < 32; j += 8)
        Wo[(size_t)(bx + ty + j) * 1024 + by + tx] = __float2half_rn(t[tx][ty + j]);
}

__global__ void pack_bias(const float* __restrict__ bk, const float* __restrict__ bv,
                          float* __restrict__ o) {
    int i = blockIdx.x * 256 + threadIdx.x;
    if (i < 1024) o[i] = bk[i];
    else if (i < 2048) o[i] = bv[i - 1024];
}

// ---------------- kv via tensor cores (+ fused ksum partials) ----------------
#define KVST 72
__global__ void __launch_bounds__(128) kv_tc(const __half* __restrict__ Kh,
                                             const __half* __restrict__ Vh,
                                             float* __restrict__ kvp,
                                             float* __restrict__ ksp) {
    const int bh = blockIdx.x, ch = blockIdx.y;
    const int b = bh >> 4, h = bh & 15;
    __shared__ __half Ks[64 * KVST];
    __shared__ __half Vs[64 * KVST];

    const int tid = threadIdx.x;
    const int lane = tid & 31, w = tid >> 5;
    const int d0 = w * 16;
    const int g = lane >> 3, r = lane & 7;

    uint32_t ksb, vsb;
    asm("{ .reg .u64 t; cvta.to.shared.u64 t, %1; cvt.u32.u64 %0, t; }" : "=r"(ksb) : "l"(Ks));
    asm("{ .reg .u64 t; cvta.to.shared.u64 t, %1; cvt.u32.u64 %0, t; }" : "=r"(vsb) : "l"(Vs));

    const uint32_t aLane = (uint32_t)(((((g >> 1) & 1) * 8 + r) * KVST + d0 + (g & 1) * 8) * 2);
    const uint32_t bLane = (uint32_t)((((g & 1) * 8 + r) * KVST + ((g >> 1) & 1) * 8) * 2);

    float acc[8][4];
#pragma unroll
    for (int i = 0; i < 8; i++)
#pragma unroll
        for (int j = 0; j < 4; j++) acc[i][j] = 0.0f;
    float kssum = 0.0f;

    const __half* Kbase = Kh + (size_t)b * SEQ * D_MODEL + h * 64;
    const __half* Vbase = Vh + (size_t)b * SEQ * D_MODEL + h * 64;
    const int sBeg = ch * (SEQ / KCH);

    for (int t = 0; t < (SEQ / KCH) / 64; t++) {
        for (int j = 0; j < 4; j++) {
            int c = tid + j * 128;
            int row = c >> 3, col8 = (c & 7) * 8;
            const size_t gidx = (size_t)(sBeg + t * 64 + row) * 1024 + col8;
            *(uint4*)&Ks[row * KVST + col8] = *(const uint4*)(Kbase + gidx);
            *(uint4*)&Vs[row * KVST + col8] = *(const uint4*)(Vbase + gidx);
        }
        __syncthreads();

        if (tid < 64) {
#pragma unroll 8
            for (int rr = 0; rr < 64; rr++) kssum += __half2float(Ks[rr * KVST + tid]);
        }

#pragma unroll
        for (int kk = 0; kk < 4; kk++) {
            uint32_t a[4];
            uint32_t aaddr = ksb + aLane + (uint32_t)(kk * 16 * KVST * 2);
            asm volatile(
                "ldmatrix.sync.aligned.m8n8.x4.trans.shared.b16 {%0,%1,%2,%3}, [%4];"
                : "=r"(a[0]), "=r"(a[1]), "=r"(a[2]), "=r"(a[3]) : "r"(aaddr));
            uint32_t bf[8][2];
#pragma unroll
            for (int nfp = 0; nfp < 4; nfp++) {
                uint32_t baddr = vsb + bLane + (uint32_t)((kk * 16 * KVST + nfp * 16) * 2);
                asm volatile(
                    "ldmatrix.sync.aligned.m8n8.x4.trans.shared.b16 {%0,%1,%2,%3}, [%4];"
                    : "=r"(bf[nfp * 2][0]), "=r"(bf[nfp * 2][1]),
                      "=r"(bf[nfp * 2 + 1][0]), "=r"(bf[nfp * 2 + 1][1])
                    : "r"(baddr));
            }
#pragma unroll
            for (int nf = 0; nf < 8; nf++)
                HMMA(acc[nf], a, bf[nf][0], bf[nf][1]);
        }
        __syncthreads();
    }

    float* kvo = kvp + ((size_t)ch * 64 + bh) * 4096;
    const int gr = lane >> 2, gc2 = (lane & 3) * 2;
#pragma unroll
    for (int nf = 0; nf < 8; nf++) {
        int col = nf * 8 + gc2;
        *(float2*)(kvo + (d0 + gr) * 64 + col) = make_float2(acc[nf][0], acc[nf][1]);
        *(float2*)(kvo + (d0 + gr + 8) * 64 + col) = make_float2(acc[nf][2], acc[nf][3]);
    }
    if (tid < 64) ksp[((size_t)ch * 64 + bh) * 64 + tid] = kssum;
}

__global__ void reduce_kv(const float* __restrict__ kvp, const float* __restrict__ ksp,
                          __half* __restrict__ kvTh, float* __restrict__ ks) {
    int i = blockIdx.x * 256 + threadIdx.x;
    int bh = i >> 12, idx = i & 4095;
    int d = idx >> 6, e = idx & 63;
    float s = 0.f;
#pragma unroll
    for (int c = 0; c < KCH; c++) s += kvp[((size_t)c * 64 + bh) * 4096 + idx];
    kvTh[(size_t)bh * 4096 + e * 64 + d] = __float2half_rn(s);
    if (i < 64 * 64) {
        int bh2 = i >> 6, d2 = i & 63;
        float t = 0.f;
#pragma unroll
        for (int c = 0; c < KCH; c++) t += ksp[((size_t)c * 64 + bh2) * 64 + d2];
        ks[i] = t;
    }
}

// ---------------- attention: 128 seq rows per block, kv tile resident ----------------
__global__ void __launch_bounds__(128) attn_tc(const __half* __restrict__ Qh,
                                               const __half* __restrict__ kvTh,
                                               const float* __restrict__ ksum,
                                               __half* __restrict__ Ah) {
    const int bh = blockIdx.x;
    const int b = bh >> 4, h = bh & 15;
    const int sBase = blockIdx.y * 128;
    __shared__ __half qs[64 * KVST];
    __shared__ __half kvs[64 * KVST];
    __shared__ float kss[64];

    const int tid = threadIdx.x;
    const int lane = tid & 31, w = tid >> 5;
    const int m0w = w * 16;

    uint32_t qsb, kvb;
    asm("{ .reg .u64 t; cvta.to.shared.u64 t, %1; cvt.u32.u64 %0, t; }" : "=r"(qsb) : "l"(qs));
    asm("{ .reg .u64 t; cvta.to.shared.u64 t, %1; cvt.u32.u64 %0, t; }" : "=r"(kvb) : "l"(kvs));

    // kv tile + ksum resident across both passes
    for (int j = 0; j < 4; j++) {
        int c = tid + j * 128;
        int row = c >> 3, col8 = (c & 7) * 8;
        *(uint4*)&kvs[row * KVST + col8] =
            *(const uint4*)(kvTh + (size_t)bh * 4096 + row * 64 + col8);
    }
    if (tid < 64) kss[tid] = ksum[bh * 64 + tid];

    const uint32_t aLane = (uint32_t)(((m0w + (lane & 15)) * KVST + (lane >> 4) * 8) * 2);
    const uint32_t bLane = (uint32_t)(((((lane >> 4) & 1) * 8 + (lane & 7)) * KVST +
                                       ((lane >> 3) & 1) * 8) * 2);
    const int gr = lane >> 2, gc2 = (lane & 3) * 2;

#pragma unroll
    for (int half = 0; half < 2; half++) {
        const int s0 = sBase + half * 64;
        // load q tile for this half
        for (int j = 0; j < 4; j++) {
            int c = tid + j * 128;
            int row = c >> 3, col8 = (c & 7) * 8;
            *(uint4*)&qs[row * KVST + col8] =
                *(const uint4*)(Qh + (size_t)(b * SEQ + s0 + row) * 1024 + h * 64 + col8);
        }
        __syncthreads();

        float acc[8][4];
#pragma unroll
        for (int i = 0; i < 8; i++)
#pragma unroll
            for (int j = 0; j < 4; j++) acc[i][j] = 0.0f;

#pragma unroll
        for (int kk = 0; kk < 4; kk++) {
            uint32_t a[4];
            LDMX4(a, qsb + aLane + (uint32_t)(kk * 32));
            uint32_t bf[8][2];
#pragma unroll
            for (int nfp = 0; nfp < 4; nfp++) {
                uint32_t baddr = kvb + bLane + (uint32_t)((nfp * 16 * KVST + kk * 16) * 2);
                asm volatile(
                    "ldmatrix.sync.aligned.m8n8.x4.shared.b16 {%0,%1,%2,%3}, [%4];"
                    : "=r"(bf[nfp * 2][0]), "=r"(bf[nfp * 2][1]),
                      "=r"(bf[nfp * 2 + 1][0]), "=r"(bf[nfp * 2 + 1][1])
                    : "r"(baddr));
            }
#pragma unroll
            for (int nf = 0; nf < 8; nf++)
                HMMA(acc[nf], a, bf[nf][0], bf[nf][1]);
        }

        float z0 = 0.f, z1 = 0.f;
#pragma unroll 8
        for (int d = 0; d < 64; d++) {
            float kd = kss[d];
            z0 = fmaf(__half2float(qs[(m0w + gr) * KVST + d]), kd, z0);
            z1 = fmaf(__half2float(qs[(m0w + gr + 8) * KVST + d]), kd, z1);
        }
        const float iz0 = 1.0f / (z0 + EPS), iz1 = 1.0f / (z1 + EPS);

        __half* Aout = Ah + (size_t)(b * SEQ + s0 + m0w) * 1024 + h * 64;
#pragma unroll
        for (int nf = 0; nf < 8; nf++) {
            int col = nf * 8 + gc2;
            *(__half2*)(Aout + (size_t)gr * 1024 + col) =
                __floats2half2_rn(acc[nf][0] * iz0, acc[nf][1] * iz0);
            *(__half2*)(Aout + (size_t)(gr + 8) * 1024 + col) =
                __floats2half2_rn(acc[nf][2] * iz1, acc[nf][3] * iz1);
        }
        __syncthreads();   // qs reuse barrier before next half
    }
}

// ---------------- launch (R14 schedule) ----------------
extern "C" void kernel_launch(void* const* d_in, const int* in_sizes, int n_in,
                              void* d_out, int out_size) {
    const float* x  = (const float*)d_in[0];
    const float* Wq = (const float*)d_in[1];
    const float* bq = (const float*)d_in[2];
    const float* Wk = (const float*)d_in[3];
    const float* bk = (const float*)d_in[4];
    const float* Wv = (const float*)d_in[5];
    const float* bv = (const float*)d_in[6];
    const float* Wo = (const float*)d_in[7];
    const float* bo = (const float*)d_in[8];
    float* out = (float*)d_out;

    __half *Xh, *Ah, *Qh, *Kh, *Vh, *Wh, *kvTh;
    float *bkv, *kvp, *ksp, *ks;
    cudaGetSymbolAddress((void**)&Xh, g_Xh);
    cudaGetSymbolAddress((void**)&Ah, g_Ah);
    cudaGetSymbolAddress((void**)&Qh, g_Qh);
    cudaGetSymbolAddress((void**)&Kh, g_Kh);
    cudaGetSymbolAddress((void**)&Vh, g_Vh);
    cudaGetSymbolAddress((void**)&Wh, g_Wh);
    cudaGetSymbolAddress((void**)&kvTh, g_kvTh);
    cudaGetSymbolAddress((void**)&bkv, g_bkv);
    cudaGetSymbolAddress((void**)&kvp, g_kvp);
    cudaGetSymbolAddress((void**)&ksp, g_ksp);
    cudaGetSymbolAddress((void**)&ks, g_ks);

    cudaFuncSetAttribute(gemm_h256<__half>, cudaFuncAttributeMaxDynamicSharedMemorySize,
                         GEMM_SMEM);
    cudaFuncSetAttribute(gemm_h256<float>, cudaFuncAttributeMaxDynamicSharedMemorySize,
                         GEMM_SMEM);

    static cudaStream_t s1 = nullptr;
    static cudaEvent_t evPre = nullptr, evQ = nullptr;
    if (s1 == nullptr) {
        cudaStreamCreate(&s1);
        cudaEventCreateWithFlags(&evPre, cudaEventDisableTiming);
        cudaEventCreateWithFlags(&evQ, cudaEventDisableTiming);
    }

    const size_t WN = (size_t)D_MODEL * D_MODEL;

    to_half_kernel<<<NTOK * D_MODEL / 4 / 256, 256>>>((const float4*)x, (__half2*)Xh,
                                                      NTOK * D_MODEL / 4);
    transpose_half4<<<dim3(32, 32, 4), dim3(32, 8)>>>(Wq, Wk, Wv, Wo, Wh);
    pack_bias<<<8, 256>>>(bk, bv, bkv);

    // fork: Q projection on side stream, KV projection + kv chain on main stream
    cudaEventRecord(evPre, 0);
    cudaStreamWaitEvent(s1, evPre, 0);
    gemm_h256<__half><<<dim3(8, 128), 256, GEMM_SMEM, s1>>>(Xh, Wh + 0 * WN, bq,
                                                            Qh, Qh, 1, 1);
    cudaEventRecord(evQ, s1);

    gemm_h256<__half><<<dim3(16, 128), 256, GEMM_SMEM>>>(Xh, Wh + 1 * WN, bkv,
                                                         Kh, Vh, 1, 0);
    kv_tc<<<dim3(64, KCH), 128>>>(Kh, Vh, kvp, ksp);
    reduce_kv<<<(64 * 4096) / 256, 256>>>(kvp, ksp, kvTh, ks);

    cudaStreamWaitEvent(0, evQ, 0);
    attn_tc<<<dim3(64, SEQ / 128), 128>>>(Qh, kvTh, ks, Ah);
    gemm_h256<float><<<dim3(8, 128), 256, GEMM_SMEM>>>(Ah, Wh + 3 * WN, bo,
                                                       out, out, 0, 0);
}

// round 16
// speedup vs baseline: 1.0353x; 1.0353x over previous
#include <cuda_runtime.h>
#include <cuda_fp16.h>
#include <math.h>
#include <stdint.h>

#define D_MODEL 1024
#define SEQ     4096
#define BATCH   4
#define NTOK    16384
#define NHEADS  16
#define EPS     1e-6f
#define KCH     8

// ---------------- scratch ----------------
__device__ __half g_Xh[(size_t)NTOK * D_MODEL];
__device__ __half g_Ah[(size_t)NTOK * D_MODEL];
__device__ __half g_Qh[(size_t)NTOK * D_MODEL];
__device__ __half g_Kh[(size_t)NTOK * D_MODEL];
__device__ __half g_Vh[(size_t)NTOK * D_MODEL];
__device__ __half g_Wh[4][(size_t)D_MODEL * D_MODEL];   // transposed [n][k]
__device__ float  g_bkv[2 * D_MODEL];
__device__ float  g_kvp[KCH * 64 * 4096];
__device__ float  g_ksp[KCH * 64 * 64];
__device__ __half g_kvTh[64 * 4096];                    // kv^T per bh: [e][d]
__device__ float  g_ks[64 * 64];

// ---------------- fp16 TC GEMM: 256 thr, warp tile 64x32, K-tile 64 ----------------
// 8 warps (2 m x 4 n), 2 CTAs/SM -> 16 warps/SM (4/SMSP) for latency coverage.
#define RS     72
#define RSB    144
#define MATB   (128 * RSB)
#define STAGEB (2 * MATB)
#define NSTAGE 3
#define GEMM_SMEM (NSTAGE * STAGEB)
#define NKT    16

__device__ __forceinline__ void cpasync16(uint32_t dst, const void* src) {
    asm volatile("cp.async.cg.shared.global [%0], [%1], 16;\n" ::"r"(dst), "l"(src));
}

__device__ __forceinline__ void load_tile(uint32_t sst, const __half* __restrict__ A,
                                          const __half* __restrict__ Bt,
                                          int m0, int n0, int kt, int tid) {
    const __half* Asrc = A + (size_t)m0 * 1024 + kt * 64;
    const __half* Bsrc = Bt + (size_t)n0 * 1024 + kt * 64;
#pragma unroll
    for (int j = 0; j < 4; j++) {
        int c = tid + j * 256;
        int row = c >> 3, kc = (c & 7) * 8;
        cpasync16(sst + (uint32_t)(row * RSB + kc * 2), Asrc + (size_t)row * 1024 + kc);
    }
#pragma unroll
    for (int j = 0; j < 4; j++) {
        int c = tid + j * 256;
        int row = c >> 3, kc = (c & 7) * 8;
        cpasync16(sst + (uint32_t)(MATB + row * RSB + kc * 2),
                  Bsrc + (size_t)row * 1024 + kc);
    }
    asm volatile("cp.async.commit_group;\n" ::: "memory");
}

#define LDMX4(dst, addr)                                                       \
    asm volatile("ldmatrix.sync.aligned.m8n8.x4.shared.b16 {%0,%1,%2,%3}, [%4];" \
                 : "=r"((dst)[0]), "=r"((dst)[1]), "=r"((dst)[2]), "=r"((dst)[3]) \
                 : "r"(addr))

#define HMMA(acc, a, b0r, b1r)                                                 \
    asm volatile("mma.sync.aligned.m16n8k16.row.col.f32.f16.f16.f32 "          \
                 "{%0,%1,%2,%3}, {%4,%5,%6,%7}, {%8,%9}, {%0,%1,%2,%3};"       \
                 : "+f"((acc)[0]), "+f"((acc)[1]), "+f"((acc)[2]), "+f"((acc)[3]) \
                 : "r"((a)[0]), "r"((a)[1]), "r"((a)[2]), "r"((a)[3]),          \
                   "r"(b0r), "r"(b1r))

// seg 0: n0 in [0,1024) -> C0 with fmap0 ; seg 1: n0 in [1024,2048) -> C1 with fmap1
template <typename OutT>
__global__ void __launch_bounds__(256, 2) gemm_h256(const __half* __restrict__ A,
                                                    const __half* __restrict__ Bt,
                                                    const float* __restrict__ bias,
                                                    OutT* __restrict__ C0,
                                                    OutT* __restrict__ C1,
                                                    int fmap0, int fmap1) {
    extern __shared__ __align__(128) char smem[];
    uint32_t sb;
    asm("{ .reg .u64 t; cvta.to.shared.u64 t, %1; cvt.u32.u64 %0, t; }" : "=r"(sb) : "l"(smem));

    const int tid = threadIdx.x;
    const int lane = tid & 31, w = tid >> 5;
    const int wm = w & 1;       // m offset *64
    const int wn = w >> 1;      // n offset *32 (0..3)
    const int m0 = blockIdx.y * 128, n0 = blockIdx.x * 128;

    const uint32_t aOff = (uint32_t)(((wm * 64 + (lane & 15)) * RS + (lane >> 4) * 8) * 2);
    const uint32_t bOff = (uint32_t)(MATB +
                                     ((wn * 32 + ((lane >> 4) & 1) * 8 + (lane & 7)) * RS +
                                      ((lane >> 3) & 1) * 8) * 2);

    float acc[4][4][4];
#pragma unroll
    for (int i = 0; i < 4; i++)
#pragma unroll
        for (int j = 0; j < 4; j++)
#pragma unroll
            for (int r = 0; r < 4; r++) acc[i][j][r] = 0.0f;

    load_tile(sb, A, Bt, m0, n0, 0, tid);
    load_tile(sb + STAGEB, A, Bt, m0, n0, 1, tid);

    int st = 0;
    for (int kt = 0; kt < NKT; kt++) {
        if (kt < NKT - 1)
            asm volatile("cp.async.wait_group 1;\n" ::: "memory");
        else
            asm volatile("cp.async.wait_group 0;\n" ::: "memory");
        __syncthreads();
        if (kt + 2 < NKT) {
            int nst = st + 2; if (nst >= NSTAGE) nst -= NSTAGE;
            load_tile(sb + (uint32_t)nst * STAGEB, A, Bt, m0, n0, kt + 2, tid);
        }
        const uint32_t cs = sb + (uint32_t)st * STAGEB;

#pragma unroll
        for (int ks = 0; ks < 4; ks++) {
            uint32_t a[4][4];
#pragma unroll
            for (int mf = 0; mf < 4; mf++)
                LDMX4(a[mf], cs + aOff + (uint32_t)(mf * 16 * RSB + ks * 32));
#pragma unroll
            for (int nfp = 0; nfp < 2; nfp++) {
                uint32_t b[4];
                LDMX4(b, cs + bOff + (uint32_t)(nfp * 16 * RSB + ks * 32));
#pragma unroll
                for (int mf = 0; mf < 4; mf++) {
                    HMMA(acc[mf][nfp * 2], a[mf], b[0], b[1]);
                    HMMA(acc[mf][nfp * 2 + 1], a[mf], b[2], b[3]);
                }
            }
        }
        st++; if (st >= NSTAGE) st -= NSTAGE;
    }

    OutT* C = (n0 < 1024) ? C0 : C1;
    const int ncol0 = (n0 < 1024) ? n0 : n0 - 1024;
    const bool fmap = (n0 < 1024) ? (fmap0 != 0) : (fmap1 != 0);

    const int gr = lane >> 2, gc2 = (lane & 3) * 2;
#pragma unroll
    for (int mf = 0; mf < 4; mf++) {
        int r0 = m0 + wm * 64 + mf * 16 + gr;
#pragma unroll
        for (int nf = 0; nf < 4; nf++) {
            int colg = n0 + wn * 32 + nf * 8 + gc2;
            int col = ncol0 + wn * 32 + nf * 8 + gc2;
            float2 bb = *(const float2*)(bias + colg);
            float v0 = acc[mf][nf][0] + bb.x;
            float v1 = acc[mf][nf][1] + bb.y;
            float v2 = acc[mf][nf][2] + bb.x;
            float v3 = acc[mf][nf][3] + bb.y;
            if (fmap) {
                v0 = (v0 > 0.0f) ? v0 + 1.0f : expf(v0);
                v1 = (v1 > 0.0f) ? v1 + 1.0f : expf(v1);
                v2 = (v2 > 0.0f) ? v2 + 1.0f : expf(v2);
                v3 = (v3 > 0.0f) ? v3 + 1.0f : expf(v3);
            }
            if (sizeof(OutT) == 2) {
                *(__half2*)((__half*)C + (size_t)r0 * 1024 + col) = __floats2half2_rn(v0, v1);
                *(__half2*)((__half*)C + (size_t)(r0 + 8) * 1024 + col) = __floats2half2_rn(v2, v3);
            } else {
                float2 o0 = {v0, v1}, o1 = {v2, v3};
                *(float2*)((float*)C + (size_t)r0 * 1024 + col) = o0;
                *(float2*)((float*)C + (size_t)(r0 + 8) * 1024 + col) = o1;
            }
        }
    }
}

// ---------------- conversions ----------------
__global__ void to_half_kernel(const float4* __restrict__ in, __half2* __restrict__ out,
                               int n4) {
    int i = blockIdx.x * blockDim.x + threadIdx.x;
    if (i >= n4) return;
    float4 v = in[i];
    out[i * 2]     = __floats2half2_rn(v.x, v.y);
    out[i * 2 + 1] = __floats2half2_rn(v.z, v.w);
}

__global__ void transpose_half4(const float* __restrict__ W0, const float* __restrict__ W1,
                                const float* __restrict__ W2, const float* __restrict__ W3,
                                __half* __restrict__ Wt) {
    const float* W = (blockIdx.z == 0) ? W0 : (blockIdx.z == 1) ? W1
                     : (blockIdx.z == 2) ? W2 : W3;
    __half* Wo = Wt + (size_t)blockIdx.z * D_MODEL * D_MODEL;
    __shared__ float t[32][33];
    const int bx = blockIdx.x * 32, by = blockIdx.y * 32;
    const int tx = threadIdx.x, ty = threadIdx.y;
#pragma unroll
    for (int j = 0; j < 32; j += 8)
        t[ty + j][tx] = W[(size_t)(by + ty + j) * 1024 + bx + tx];
    __syncthreads();
#pragma unroll
    for (int j = 0; j < 32; j += 8)
        Wo[(size_t)(bx + ty + j) * 1024 + by + tx] = __float2half_rn(t[tx][ty + j]);
}

__global__ void pack_bias(const float* __restrict__ bk, const float* __restrict__ bv,
                          float* __restrict__ o) {
    int i = blockIdx.x * 256 + threadIdx.x;
    if (i < 1024) o[i] = bk[i];
    else if (i < 2048) o[i] = bv[i - 1024];
}

// ---------------- kv via tensor cores (+ fused ksum partials) ----------------
#define KVST 72
__global__ void __launch_bounds__(128) kv_tc(const __half* __restrict__ Kh,
                                             const __half* __restrict__ Vh,
                                             float* __restrict__ kvp,
                                             float* __restrict__ ksp) {
    const int bh = blockIdx.x, ch = blockIdx.y;
    const int b = bh >> 4, h = bh & 15;
    __shared__ __half Ks[64 * KVST];
    __shared__ __half Vs[64 * KVST];

    const int tid = threadIdx.x;
    const int lane = tid & 31, w = tid >> 5;
    const int d0 = w * 16;
    const int g = lane >> 3, r = lane & 7;

    uint32_t ksb, vsb;
    asm("{ .reg .u64 t; cvta.to.shared.u64 t, %1; cvt.u32.u64 %0, t; }" : "=r"(ksb) : "l"(Ks));
    asm("{ .reg .u64 t; cvta.to.shared.u64 t, %1; cvt.u32.u64 %0, t; }" : "=r"(vsb) : "l"(Vs));

    const uint32_t aLane = (uint32_t)(((((g >> 1) & 1) * 8 + r) * KVST + d0 + (g & 1) * 8) * 2);
    const uint32_t bLane = (uint32_t)((((g & 1) * 8 + r) * KVST + ((g >> 1) & 1) * 8) * 2);

    float acc[8][4];
#pragma unroll
    for (int i = 0; i < 8; i++)
#pragma unroll
        for (int j = 0; j < 4; j++) acc[i][j] = 0.0f;
    float kssum = 0.0f;

    const __half* Kbase = Kh + (size_t)b * SEQ * D_MODEL + h * 64;
    const __half* Vbase = Vh + (size_t)b * SEQ * D_MODEL + h * 64;
    const int sBeg = ch * (SEQ / KCH);

    for (int t = 0; t < (SEQ / KCH) / 64; t++) {
        for (int j = 0; j < 4; j++) {
            int c = tid + j * 128;
            int row = c >> 3, col8 = (c & 7) * 8;
            const size_t gidx = (size_t)(sBeg + t * 64 + row) * 1024 + col8;
            *(uint4*)&Ks[row * KVST + col8] = *(const uint4*)(Kbase + gidx);
            *(uint4*)&Vs[row * KVST + col8] = *(const uint4*)(Vbase + gidx);
        }
        __syncthreads();

        if (tid < 64) {
#pragma unroll 8
            for (int rr = 0; rr < 64; rr++) kssum += __half2float(Ks[rr * KVST + tid]);
        }

#pragma unroll
        for (int kk = 0; kk < 4; kk++) {
            uint32_t a[4];
            uint32_t aaddr = ksb + aLane + (uint32_t)(kk * 16 * KVST * 2);
            asm volatile(
                "ldmatrix.sync.aligned.m8n8.x4.trans.shared.b16 {%0,%1,%2,%3}, [%4];"
                : "=r"(a[0]), "=r"(a[1]), "=r"(a[2]), "=r"(a[3]) : "r"(aaddr));
            uint32_t bf[8][2];
#pragma unroll
            for (int nfp = 0; nfp < 4; nfp++) {
                uint32_t baddr = vsb + bLane + (uint32_t)((kk * 16 * KVST + nfp * 16) * 2);
                asm volatile(
                    "ldmatrix.sync.aligned.m8n8.x4.trans.shared.b16 {%0,%1,%2,%3}, [%4];"
                    : "=r"(bf[nfp * 2][0]), "=r"(bf[nfp * 2][1]),
                      "=r"(bf[nfp * 2 + 1][0]), "=r"(bf[nfp * 2 + 1][1])
                    : "r"(baddr));
            }
#pragma unroll
            for (int nf = 0; nf < 8; nf++)
                HMMA(acc[nf], a, bf[nf][0], bf[nf][1]);
        }
        __syncthreads();
    }

    float* kvo = kvp + ((size_t)ch * 64 + bh) * 4096;
    const int gr = lane >> 2, gc2 = (lane & 3) * 2;
#pragma unroll
    for (int nf = 0; nf < 8; nf++) {
        int col = nf * 8 + gc2;
        *(float2*)(kvo + (d0 + gr) * 64 + col) = make_float2(acc[nf][0], acc[nf][1]);
        *(float2*)(kvo + (d0 + gr + 8) * 64 + col) = make_float2(acc[nf][2], acc[nf][3]);
    }
    if (tid < 64) ksp[((size_t)ch * 64 + bh) * 64 + tid] = kssum;
}

__global__ void reduce_kv(const float* __restrict__ kvp, const float* __restrict__ ksp,
                          __half* __restrict__ kvTh, float* __restrict__ ks) {
    int i = blockIdx.x * 256 + threadIdx.x;
    int bh = i >> 12, idx = i & 4095;
    int d = idx >> 6, e = idx & 63;
    float s = 0.f;
#pragma unroll
    for (int c = 0; c < KCH; c++) s += kvp[((size_t)c * 64 + bh) * 4096 + idx];
    kvTh[(size_t)bh * 4096 + e * 64 + d] = __float2half_rn(s);
    if (i < 64 * 64) {
        int bh2 = i >> 6, d2 = i & 63;
        float t = 0.f;
#pragma unroll
        for (int c = 0; c < KCH; c++) t += ksp[((size_t)c * 64 + bh2) * 64 + d2];
        ks[i] = t;
    }
}

__global__ void __launch_bounds__(128) attn_tc(const __half* __restrict__ Qh,
                                               const __half* __restrict__ kvTh,
                                               const float* __restrict__ ksum,
                                               __half* __restrict__ Ah) {
    const int bh = blockIdx.x;
    const int b = bh >> 4, h = bh & 15;
    const int s0 = blockIdx.y * 64;
    __shared__ __half qs[64 * KVST];
    __shared__ __half kvs[64 * KVST];
    __shared__ float kss[64];

    const int tid = threadIdx.x;
    const int lane = tid & 31, w = tid >> 5;
    const int m0w = w * 16;

    uint32_t qsb, kvb;
    asm("{ .reg .u64 t; cvta.to.shared.u64 t, %1; cvt.u32.u64 %0, t; }" : "=r"(qsb) : "l"(qs));
    asm("{ .reg .u64 t; cvta.to.shared.u64 t, %1; cvt.u32.u64 %0, t; }" : "=r"(kvb) : "l"(kvs));

    for (int j = 0; j < 4; j++) {
        int c = tid + j * 128;
        int row = c >> 3, col8 = (c & 7) * 8;
        *(uint4*)&qs[row * KVST + col8] =
            *(const uint4*)(Qh + (size_t)(b * SEQ + s0 + row) * 1024 + h * 64 + col8);
        *(uint4*)&kvs[row * KVST + col8] =
            *(const uint4*)(kvTh + (size_t)bh * 4096 + row * 64 + col8);
    }
    if (tid < 64) kss[tid] = ksum[bh * 64 + tid];
    __syncthreads();

    const uint32_t aLane = (uint32_t)(((m0w + (lane & 15)) * KVST + (lane >> 4) * 8) * 2);
    const uint32_t bLane = (uint32_t)(((((lane >> 4) & 1) * 8 + (lane & 7)) * KVST +
                                       ((lane >> 3) & 1) * 8) * 2);

    float acc[8][4];
#pragma unroll
    for (int i = 0; i < 8; i++)
#pragma unroll
        for (int j = 0; j < 4; j++) acc[i][j] = 0.0f;

#pragma unroll
    for (int kk = 0; kk < 4; kk++) {
        uint32_t a[4];
        LDMX4(a, qsb + aLane + (uint32_t)(kk * 32));
        uint32_t bf[8][2];
#pragma unroll
        for (int nfp = 0; nfp < 4; nfp++) {
            uint32_t baddr = kvb + bLane + (uint32_t)((nfp * 16 * KVST + kk * 16) * 2);
            asm volatile(
                "ldmatrix.sync.aligned.m8n8.x4.shared.b16 {%0,%1,%2,%3}, [%4];"
                : "=r"(bf[nfp * 2][0]), "=r"(bf[nfp * 2][1]),
                  "=r"(bf[nfp * 2 + 1][0]), "=r"(bf[nfp * 2 + 1][1])
                : "r"(baddr));
        }
#pragma unroll
        for (int nf = 0; nf < 8; nf++)
            HMMA(acc[nf], a, bf[nf][0], bf[nf][1]);
    }

    const int gr = lane >> 2, gc2 = (lane & 3) * 2;
    float z0 = 0.f, z1 = 0.f;
#pragma unroll 8
    for (int d = 0; d < 64; d++) {
        float kd = kss[d];
        z0 = fmaf(__half2float(qs[(m0w + gr) * KVST + d]), kd, z0);
        z1 = fmaf(__half2float(qs[(m0w + gr + 8) * KVST + d]), kd, z1);
    }
    const float iz0 = 1.0f / (z0 + EPS), iz1 = 1.0f / (z1 + EPS);

    __half* Aout = Ah + (size_t)(b * SEQ + s0 + m0w) * 1024 + h * 64;
#pragma unroll
    for (int nf = 0; nf < 8; nf++) {
        int col = nf * 8 + gc2;
        *(__half2*)(Aout + (size_t)gr * 1024 + col) =
            __floats2half2_rn(acc[nf][0] * iz0, acc[nf][1] * iz0);
        *(__half2*)(Aout + (size_t)(gr + 8) * 1024 + col) =
            __floats2half2_rn(acc[nf][2] * iz1, acc[nf][3] * iz1);
    }
}

// ---------------- launch (R11 schedule) ----------------
extern "C" void kernel_launch(void* const* d_in, const int* in_sizes, int n_in,
                              void* d_out, int out_size) {
    const float* x  = (const float*)d_in[0];
    const float* Wq = (const float*)d_in[1];
    const float* bq = (const float*)d_in[2];
    const float* Wk = (const float*)d_in[3];
    const float* bk = (const float*)d_in[4];
    const float* Wv = (const float*)d_in[5];
    const float* bv = (const float*)d_in[6];
    const float* Wo = (const float*)d_in[7];
    const float* bo = (const float*)d_in[8];
    float* out = (float*)d_out;

    __half *Xh, *Ah, *Qh, *Kh, *Vh, *Wh, *kvTh;
    float *bkv, *kvp, *ksp, *ks;
    cudaGetSymbolAddress((void**)&Xh, g_Xh);
    cudaGetSymbolAddress((void**)&Ah, g_Ah);
    cudaGetSymbolAddress((void**)&Qh, g_Qh);
    cudaGetSymbolAddress((void**)&Kh, g_Kh);
    cudaGetSymbolAddress((void**)&Vh, g_Vh);
    cudaGetSymbolAddress((void**)&Wh, g_Wh);
    cudaGetSymbolAddress((void**)&kvTh, g_kvTh);
    cudaGetSymbolAddress((void**)&bkv, g_bkv);
    cudaGetSymbolAddress((void**)&kvp, g_kvp);
    cudaGetSymbolAddress((void**)&ksp, g_ksp);
    cudaGetSymbolAddress((void**)&ks, g_ks);

    cudaFuncSetAttribute(gemm_h256<__half>, cudaFuncAttributeMaxDynamicSharedMemorySize,
                         GEMM_SMEM);
    cudaFuncSetAttribute(gemm_h256<float>, cudaFuncAttributeMaxDynamicSharedMemorySize,
                         GEMM_SMEM);

    static cudaStream_t s1 = nullptr;
    static cudaEvent_t evPre = nullptr, evQ = nullptr;
    if (s1 == nullptr) {
        cudaStreamCreate(&s1);
        cudaEventCreateWithFlags(&evPre, cudaEventDisableTiming);
        cudaEventCreateWithFlags(&evQ, cudaEventDisableTiming);
    }

    const size_t WN = (size_t)D_MODEL * D_MODEL;

    to_half_kernel<<<NTOK * D_MODEL / 4 / 256, 256>>>((const float4*)x, (__half2*)Xh,
                                                      NTOK * D_MODEL / 4);
    transpose_half4<<<dim3(32, 32, 4), dim3(32, 8)>>>(Wq, Wk, Wv, Wo, Wh);
    pack_bias<<<8, 256>>>(bk, bv, bkv);

    // fork: Q projection on side stream, KV projection + kv chain on main stream
    cudaEventRecord(evPre, 0);
    cudaStreamWaitEvent(s1, evPre, 0);
    gemm_h256<__half><<<dim3(8, 128), 256, GEMM_SMEM, s1>>>(Xh, Wh + 0 * WN, bq,
                                                            Qh, Qh, 1, 1);
    cudaEventRecord(evQ, s1);

    gemm_h256<__half><<<dim3(16, 128), 256, GEMM_SMEM>>>(Xh, Wh + 1 * WN, bkv,
                                                         Kh, Vh, 1, 0);
    kv_tc<<<dim3(64, KCH), 128>>>(Kh, Vh, kvp, ksp);
    reduce_kv<<<(64 * 4096) / 256, 256>>>(kvp, ksp, kvTh, ks);

    cudaStreamWaitEvent(0, evQ, 0);
    attn_tc<<<dim3(64, SEQ / 64), 128>>>(Qh, kvTh, ks, Ah);
    gemm_h256<float><<<dim3(8, 128), 256, GEMM_SMEM>>>(Ah, Wh + 3 * WN, bo,
                                                       out, out, 0, 0);
}